// round 6
// baseline (speedup 1.0000x reference)
#include <cuda_runtime.h>
#include <cuda_bf16.h>
#include <cstdint>

#define BB   4
#define TLEN 1024
#define EE   1024
#define NH   16
#define HD   64
#define SCALING 0.125f   // 64^-0.5

// ---------------- scratch (static device arrays; no runtime allocation) ----
__device__ float g_maskval[BB*TLEN];
__device__ int   g_mask_kind;

#define ACT_ELEMS (4096*1024)
#define W_ELEMS   (1024*1024)
__device__ unsigned short g_xq_h[ACT_ELEMS], g_xq_l[ACT_ELEMS];
__device__ unsigned short g_xk_h[ACT_ELEMS], g_xk_l[ACT_ELEMS];
__device__ unsigned short g_xv_h[ACT_ELEMS], g_xv_l[ACT_ELEMS];
__device__ unsigned short g_cx_h[ACT_ELEMS], g_cx_l[ACT_ELEMS];
__device__ unsigned short g_wq_h[W_ELEMS], g_wq_l[W_ELEMS];
__device__ unsigned short g_wk_h[W_ELEMS], g_wk_l[W_ELEMS];
__device__ unsigned short g_wv_h[W_ELEMS], g_wv_l[W_ELEMS];
__device__ unsigned short g_wo_h[W_ELEMS], g_wo_l[W_ELEMS];
// projected Q/K/V, pre-split bf16 hi/lo, [B,H,T,D]
__device__ unsigned short g_qh[ACT_ELEMS], g_ql[ACT_ELEMS];
__device__ unsigned short g_kh[ACT_ELEMS], g_kl[ACT_ELEMS];
__device__ unsigned short g_vh[ACT_ELEMS], g_vl[ACT_ELEMS];

// ---------------- warp-mma helpers -----------------------------------------
__device__ __forceinline__ uint32_t smem_u32(const void* p) {
    uint32_t a;
    asm("{ .reg .u64 t; cvta.to.shared.u64 t, %1; cvt.u32.u64 %0, t; }"
        : "=r"(a) : "l"(p));
    return a;
}

__device__ __forceinline__ void ldsm_x4(uint32_t r[4], uint32_t addr) {
    asm volatile("ldmatrix.sync.aligned.m8n8.x4.shared.b16 {%0,%1,%2,%3}, [%4];"
        : "=r"(r[0]), "=r"(r[1]), "=r"(r[2]), "=r"(r[3]) : "r"(addr));
}

__device__ __forceinline__ void ldsm_x4_t(uint32_t r[4], uint32_t addr) {
    asm volatile("ldmatrix.sync.aligned.m8n8.x4.trans.shared.b16 {%0,%1,%2,%3}, [%4];"
        : "=r"(r[0]), "=r"(r[1]), "=r"(r[2]), "=r"(r[3]) : "r"(addr));
}

__device__ __forceinline__ void mma_bf16(float c[4], const uint32_t a[4],
                                         const uint32_t b[2]) {
    asm volatile(
        "mma.sync.aligned.m16n8k16.row.col.f32.bf16.bf16.f32 "
        "{%0,%1,%2,%3}, {%4,%5,%6,%7}, {%8,%9}, {%0,%1,%2,%3};"
        : "+f"(c[0]), "+f"(c[1]), "+f"(c[2]), "+f"(c[3])
        : "r"(a[0]), "r"(a[1]), "r"(a[2]), "r"(a[3]), "r"(b[0]), "r"(b[1]));
}

__device__ __forceinline__ uint32_t pack_bf16x2(float lo, float hi) {
    uint32_t r;
    asm("cvt.rn.bf16x2.f32 %0, %1, %2;" : "=r"(r) : "f"(hi), "f"(lo));
    return r;
}

__device__ __forceinline__ float bf16_round(float x) {
    return __bfloat162float(__float2bfloat16_rn(x));
}

__device__ __forceinline__ void cp_async16(uint32_t smem_addr, const void* gptr) {
    asm volatile("cp.async.cg.shared.global [%0], [%1], 16;"
        :: "r"(smem_addr), "l"(gptr));
}
#define CP_COMMIT() asm volatile("cp.async.commit_group;" ::: "memory")
#define CP_WAIT(n)  asm volatile("cp.async.wait_group %0;" :: "n"(n) : "memory")

// ---------------- mask dtype sniffing --------------------------------------
__global__ void detect_mask_kernel(const unsigned char* __restrict__ p) {
    __shared__ int c0s, c1s;
    if (threadIdx.x == 0) { c0s = 0; c1s = 0; }
    __syncthreads();
    int c0 = 0, c1 = 0;
    for (int i = threadIdx.x; i < 1024; i += blockDim.x) {
        if (p[4 * i + 1]) c1++;
        if (p[4 * i + 0]) c0++;
    }
    if (c0) atomicAdd(&c0s, c0);
    if (c1) atomicAdd(&c1s, c1);
    __syncthreads();
    if (threadIdx.x == 0) g_mask_kind = c1s ? 1 : (c0s ? 0 : 2);
}

__global__ void expand_mask_kernel(const void* __restrict__ p) {
    int i = blockIdx.x * blockDim.x + threadIdx.x;
    if (i >= BB * TLEN) return;
    int kind = g_mask_kind;
    bool m;
    if (kind == 1)      m = ((const unsigned char*)p)[i] != 0;
    else if (kind == 0) m = ((const int*)p)[i] != 0;
    else                m = ((const float*)p)[i] != 0.0f;
    g_maskval[i] = m ? -1e30f : 0.0f;
}

// ---------------- fp32 -> bf16 hi/lo split ---------------------------------
__global__ void split_bf16_kernel(const float* __restrict__ src,
                                  unsigned short* __restrict__ hi,
                                  unsigned short* __restrict__ lo, int n4) {
    int i = blockIdx.x * blockDim.x + threadIdx.x;
    if (i >= n4) return;
    float4 v = ((const float4*)src)[i];
    float vv[4] = {v.x, v.y, v.z, v.w};
    unsigned short h[4], l[4];
#pragma unroll
    for (int j = 0; j < 4; j++) {
        __nv_bfloat16 bh = __float2bfloat16_rn(vv[j]);
        float r = vv[j] - __bfloat162float(bh);
        h[j] = __bfloat16_as_ushort(bh);
        l[j] = __bfloat16_as_ushort(__float2bfloat16_rn(r));
    }
    uint2 ph, pl;
    ph.x = (uint32_t)h[0] | ((uint32_t)h[1] << 16);
    ph.y = (uint32_t)h[2] | ((uint32_t)h[3] << 16);
    pl.x = (uint32_t)l[0] | ((uint32_t)l[1] << 16);
    pl.y = (uint32_t)l[2] | ((uint32_t)l[3] << 16);
    *(uint2*)(hi + 4 * (size_t)i) = ph;
    *(uint2*)(lo + 4 * (size_t)i) = pl;
}

// ---------------- cp.async double-buffered split-bf16 GEMM core -------------
#define GSTR 24
#define GBUF (128 * GSTR * 2)        // 6144 B per operand buffer
#define GSTAGE (4 * GBUF)            // 24576 B per stage
#define GSMEM (2 * GSTAGE)           // 49152 B total

struct QKVArgs {
    const unsigned short *Ah[3], *Al[3], *Bh[3], *Bl[3];
    const float* bias[3];
    float scale[3];
    unsigned short *Ch[3], *Cl[3];
};

// shared GEMM body: computes acc for one 128x128 tile
__device__ __forceinline__ void gemm_body(
    const unsigned short* __restrict__ Ah, const unsigned short* __restrict__ Al,
    const unsigned short* __restrict__ Bh, const unsigned short* __restrict__ Bl,
    char* smem, int m0, int n0, float acc[2][8][4])
{
    const int tid = threadIdx.x, wid = tid >> 5, lane = tid & 31;
    const int warp_m = (wid & 3) * 32;
    const int warp_n = (wid >> 2) * 64;
    const uint32_t sbase = smem_u32(smem);

    const int cp_r = tid >> 1, cp_half = tid & 1;
    const uint32_t cp_soff = (uint32_t)(cp_r * (GSTR * 2) + cp_half * 16);
    const size_t cp_gA = (size_t)(m0 + cp_r) * 1024 + cp_half * 8;
    const size_t cp_gB = (size_t)(n0 + cp_r) * 1024 + cp_half * 8;

    const int a_row = warp_m + (lane & 15);
    const int a_csel = (lane >> 4) << 3;
    const int b_row = warp_n + ((lane >> 4) << 3) + (lane & 7);
    const int b_csel = ((lane >> 3) & 1) << 3;

#pragma unroll
    for (int mb = 0; mb < 2; mb++)
#pragma unroll
        for (int nb = 0; nb < 8; nb++)
#pragma unroll
            for (int q = 0; q < 4; q++) acc[mb][nb][q] = 0.0f;

    auto issue = [&](int kc) {
        uint32_t st = sbase + (kc & 1) * GSTAGE;
        size_t kofs = (size_t)kc * 16;
        cp_async16(st + 0 * GBUF + cp_soff, Ah + cp_gA + kofs);
        cp_async16(st + 1 * GBUF + cp_soff, Al + cp_gA + kofs);
        cp_async16(st + 2 * GBUF + cp_soff, Bh + cp_gB + kofs);
        cp_async16(st + 3 * GBUF + cp_soff, Bl + cp_gB + kofs);
        CP_COMMIT();
    };

    issue(0);
    for (int kc = 0; kc < 64; kc++) {
        if (kc + 1 < 64) { issue(kc + 1); CP_WAIT(1); }
        else             { CP_WAIT(0); }
        __syncthreads();

        const uint32_t st = sbase + (kc & 1) * GSTAGE;
        uint32_t afh[2][4], afl[2][4];
#pragma unroll
        for (int mb = 0; mb < 2; mb++) {
            uint32_t off = (uint32_t)(((a_row + mb * 16) * GSTR + a_csel) * 2);
            ldsm_x4(afh[mb], st + 0 * GBUF + off);
            ldsm_x4(afl[mb], st + 1 * GBUF + off);
        }
#pragma unroll
        for (int nb2 = 0; nb2 < 4; nb2++) {
            uint32_t off = (uint32_t)(((b_row + nb2 * 16) * GSTR + b_csel) * 2);
            uint32_t th[4], tl[4];
            ldsm_x4(th, st + 2 * GBUF + off);
            ldsm_x4(tl, st + 3 * GBUF + off);
            uint32_t bh0[2] = {th[0], th[1]}, bh1[2] = {th[2], th[3]};
            uint32_t bl0[2] = {tl[0], tl[1]}, bl1[2] = {tl[2], tl[3]};
#pragma unroll
            for (int mb = 0; mb < 2; mb++) {
                mma_bf16(acc[mb][nb2 * 2],     afh[mb], bh0);
                mma_bf16(acc[mb][nb2 * 2 + 1], afh[mb], bh1);
                mma_bf16(acc[mb][nb2 * 2],     afh[mb], bl0);
                mma_bf16(acc[mb][nb2 * 2 + 1], afh[mb], bl1);
                mma_bf16(acc[mb][nb2 * 2],     afl[mb], bh0);
                mma_bf16(acc[mb][nb2 * 2 + 1], afl[mb], bh1);
            }
        }
        __syncthreads();
    }
}

// merged QKV projection: grid (32, 8, 3), output pre-split [B,H,T,D]
__global__ void __launch_bounds__(256, 2) gemm_qkv_kernel(QKVArgs args)
{
    extern __shared__ char smem[];
    const int z = blockIdx.z;
    const int tid = threadIdx.x, wid = tid >> 5, lane = tid & 31;
    const int m0 = blockIdx.x * 128, n0 = blockIdx.y * 128;

    float acc[2][8][4];
    gemm_body(args.Ah[z], args.Al[z], args.Bh[z], args.Bl[z], smem, m0, n0, acc);

    const float scale = args.scale[z];
    const float* bias = args.bias[z];
    unsigned short* Ch = args.Ch[z];
    unsigned short* Cl = args.Cl[z];
    const int warp_m = (wid & 3) * 32;
    const int warp_n = (wid >> 2) * 64;
    const int g = lane >> 2, tg = lane & 3;
#pragma unroll
    for (int mb = 0; mb < 2; mb++) {
#pragma unroll
        for (int nb = 0; nb < 8; nb++) {
            int n = n0 + warp_n + nb * 8 + tg * 2;
            float b0 = bias[n], b1 = bias[n + 1];
#pragma unroll
            for (int half = 0; half < 2; half++) {
                int m = m0 + warp_m + mb * 16 + g + half * 8;
                float vx = (acc[mb][nb][half * 2 + 0] + b0) * scale;
                float vy = (acc[mb][nb][half * 2 + 1] + b1) * scale;
                int bb = m >> 10, t = m & 1023, hh = n >> 6, d = n & 63;
                size_t off = (((size_t)(bb * NH + hh)) * TLEN + t) * HD + d;
                float hx = bf16_round(vx), hy = bf16_round(vy);
                *(uint32_t*)(Ch + off) = pack_bf16x2(hx, hy);
                *(uint32_t*)(Cl + off) = pack_bf16x2(vx - hx, vy - hy);
            }
        }
    }
}

// output projection: fp32 out [M,N]
__global__ void __launch_bounds__(256, 2) gemm_out_kernel(
    const unsigned short* __restrict__ Ah, const unsigned short* __restrict__ Al,
    const unsigned short* __restrict__ Bh, const unsigned short* __restrict__ Bl,
    const float* __restrict__ bias, float* __restrict__ Cf)
{
    extern __shared__ char smem[];
    const int tid = threadIdx.x, wid = tid >> 5, lane = tid & 31;
    const int m0 = blockIdx.x * 128, n0 = blockIdx.y * 128;

    float acc[2][8][4];
    gemm_body(Ah, Al, Bh, Bl, smem, m0, n0, acc);

    const int warp_m = (wid & 3) * 32;
    const int warp_n = (wid >> 2) * 64;
    const int g = lane >> 2, tg = lane & 3;
#pragma unroll
    for (int mb = 0; mb < 2; mb++) {
#pragma unroll
        for (int nb = 0; nb < 8; nb++) {
            int n = n0 + warp_n + nb * 8 + tg * 2;
            float b0 = bias[n], b1 = bias[n + 1];
#pragma unroll
            for (int half = 0; half < 2; half++) {
                int m = m0 + warp_m + mb * 16 + g + half * 8;
                float2 v;
                v.x = acc[mb][nb][half * 2 + 0] + b0;
                v.y = acc[mb][nb][half * 2 + 1] + b1;
                *(float2*)(Cf + (size_t)m * 1024 + n) = v;
            }
        }
    }
}

// ---------------- tensor-core flash attention (128-row query tiles) ---------
// CTA: 256 threads (8 warps), 128 query rows of one (b,h). Grid (8,16,4).
#define FPAD 72
#define QBUF (128 * FPAD * 2)   // 18432 B per Q buffer
#define KBUF (64 * FPAD * 2)    // 9216 B per K/V buffer

__global__ void __launch_bounds__(256) flash_mma_kernel(
    const float* __restrict__ attn_bias)
{
    extern __shared__ char sm[];
    unsigned short* sQh = (unsigned short*)(sm);
    unsigned short* sQl = (unsigned short*)(sm + QBUF);
    unsigned short* sKh = (unsigned short*)(sm + 2 * QBUF);
    unsigned short* sKl = (unsigned short*)(sm + 2 * QBUF + KBUF);
    unsigned short* sVh = (unsigned short*)(sm + 2 * QBUF + 2 * KBUF);
    unsigned short* sVl = (unsigned short*)(sm + 2 * QBUF + 3 * KBUF);
    float* smask = (float*)(sm + 2 * QBUF + 4 * KBUF);

    const int tid = threadIdx.x, wid = tid >> 5, lane = tid & 31;
    const int t0 = blockIdx.x * 128, h = blockIdx.y, b = blockIdx.z;
    const int bh = b * NH + h;
    const size_t base = (size_t)bh * TLEN * HD;
    const unsigned short *qh_g = g_qh + base, *ql_g = g_ql + base;
    const unsigned short *kh_g = g_kh + base, *kl_g = g_kl + base;
    const unsigned short *vh_g = g_vh + base, *vl_g = g_vl + base;
    const float* biasbase = attn_bias + (size_t)bh * TLEN * TLEN;

    const int warp_m = wid * 16;
    const int g = lane >> 2, tq = lane & 3;

    const uint32_t sQh_b = smem_u32(sQh), sQl_b = smem_u32(sQl);
    const uint32_t sKh_b = smem_u32(sKh), sKl_b = smem_u32(sKl);
    const uint32_t sVh_b = smem_u32(sVh), sVl_b = smem_u32(sVl);

    // ---- fill Q tile (128 rows) ----
    for (int i = tid; i < 2048; i += 256) {
        int r = i >> 4, c4 = (i & 15) << 2;
        size_t go = (size_t)(t0 + r) * HD + c4;
        *(uint2*)&sQh[r * FPAD + c4] = *(const uint2*)(qh_g + go);
        *(uint2*)&sQl[r * FPAD + c4] = *(const uint2*)(ql_g + go);
    }
    __syncthreads();

    const int a_row = warp_m + (lane & 15);
    const int a_csel = (lane >> 4) << 3;
    uint32_t qh[4][4], ql[4][4];
#pragma unroll
    for (int kk = 0; kk < 4; kk++) {
        uint32_t off = (uint32_t)((a_row * FPAD + kk * 16 + a_csel) * 2);
        ldsm_x4(qh[kk], sQh_b + off);
        ldsm_x4(ql[kk], sQl_b + off);
    }

    float accO[8][4];
#pragma unroll
    for (int nb = 0; nb < 8; nb++)
#pragma unroll
        for (int q = 0; q < 4; q++) accO[nb][q] = 0.0f;
    float mrow0 = -1e30f, mrow1 = -1e30f, lrow0 = 0.0f, lrow1 = 0.0f;

    const int b_rowbase = ((lane >> 4) << 3) + (lane & 7);
    const int b_csel = ((lane >> 3) & 1) << 3;
    const int v_key = (((lane >> 3) & 1) << 3) + (lane & 7);
    const int v_dof = (lane >> 4) << 3;

    for (int s0 = 0; s0 < TLEN; s0 += 64) {
        __syncthreads();
        for (int i = tid; i < 1024; i += 256) {
            int r = i >> 4, c4 = (i & 15) << 2;
            size_t go = (size_t)(s0 + r) * HD + c4;
            int so = r * FPAD + c4;
            *(uint2*)&sKh[so] = *(const uint2*)(kh_g + go);
            *(uint2*)&sKl[so] = *(const uint2*)(kl_g + go);
            *(uint2*)&sVh[so] = *(const uint2*)(vh_g + go);
            *(uint2*)&sVl[so] = *(const uint2*)(vl_g + go);
        }
        if (tid < 64) smask[tid] = g_maskval[b * TLEN + s0 + tid];
        __syncthreads();

        // ---- S = Qh*Kh + Qh*Kl + Ql*Kh ----
        float accS[8][4];
#pragma unroll
        for (int nb = 0; nb < 8; nb++)
#pragma unroll
            for (int q = 0; q < 4; q++) accS[nb][q] = 0.0f;

#pragma unroll
        for (int kk = 0; kk < 4; kk++) {
#pragma unroll
            for (int nb2 = 0; nb2 < 4; nb2++) {
                uint32_t off = (uint32_t)(((b_rowbase + nb2 * 16) * FPAD + kk * 16 + b_csel) * 2);
                uint32_t th[4], tl[4];
                ldsm_x4(th, sKh_b + off);
                ldsm_x4(tl, sKl_b + off);
                uint32_t bh0[2] = {th[0], th[1]}, bh1[2] = {th[2], th[3]};
                uint32_t bl0[2] = {tl[0], tl[1]}, bl1[2] = {tl[2], tl[3]};
                mma_bf16(accS[nb2 * 2],     qh[kk], bh0);
                mma_bf16(accS[nb2 * 2 + 1], qh[kk], bh1);
                mma_bf16(accS[nb2 * 2],     qh[kk], bl0);
                mma_bf16(accS[nb2 * 2 + 1], qh[kk], bl1);
                mma_bf16(accS[nb2 * 2],     ql[kk], bh0);
                mma_bf16(accS[nb2 * 2 + 1], ql[kk], bh1);
            }
        }

        // ---- add bias + mask ----
        const int row0 = t0 + warp_m + g;
        const int row1 = row0 + 8;
#pragma unroll
        for (int nb = 0; nb < 8; nb++) {
            int col = s0 + nb * 8 + tq * 2;
            float2 bv0 = *(const float2*)(biasbase + (size_t)row0 * TLEN + col);
            float2 bv1 = *(const float2*)(biasbase + (size_t)row1 * TLEN + col);
            float mk0 = smask[nb * 8 + tq * 2];
            float mk1 = smask[nb * 8 + tq * 2 + 1];
            accS[nb][0] += bv0.x + mk0;
            accS[nb][1] += bv0.y + mk1;
            accS[nb][2] += bv1.x + mk0;
            accS[nb][3] += bv1.y + mk1;
        }

        // ---- online softmax (quad reductions) ----
        float mx0 = mrow0, mx1 = mrow1;
#pragma unroll
        for (int nb = 0; nb < 8; nb++) {
            mx0 = fmaxf(mx0, fmaxf(accS[nb][0], accS[nb][1]));
            mx1 = fmaxf(mx1, fmaxf(accS[nb][2], accS[nb][3]));
        }
        mx0 = fmaxf(mx0, __shfl_xor_sync(0xFFFFFFFF, mx0, 1));
        mx0 = fmaxf(mx0, __shfl_xor_sync(0xFFFFFFFF, mx0, 2));
        mx1 = fmaxf(mx1, __shfl_xor_sync(0xFFFFFFFF, mx1, 1));
        mx1 = fmaxf(mx1, __shfl_xor_sync(0xFFFFFFFF, mx1, 2));
        float al0 = __expf(mrow0 - mx0), al1 = __expf(mrow1 - mx1);
        mrow0 = mx0; mrow1 = mx1;

        float sum0 = 0.0f, sum1 = 0.0f;
#pragma unroll
        for (int nb = 0; nb < 8; nb++) {
            accS[nb][0] = __expf(accS[nb][0] - mx0);
            accS[nb][1] = __expf(accS[nb][1] - mx0);
            accS[nb][2] = __expf(accS[nb][2] - mx1);
            accS[nb][3] = __expf(accS[nb][3] - mx1);
            sum0 += accS[nb][0] + accS[nb][1];
            sum1 += accS[nb][2] + accS[nb][3];
        }
        sum0 += __shfl_xor_sync(0xFFFFFFFF, sum0, 1);
        sum0 += __shfl_xor_sync(0xFFFFFFFF, sum0, 2);
        sum1 += __shfl_xor_sync(0xFFFFFFFF, sum1, 1);
        sum1 += __shfl_xor_sync(0xFFFFFFFF, sum1, 2);
        lrow0 = lrow0 * al0 + sum0;
        lrow1 = lrow1 * al1 + sum1;

#pragma unroll
        for (int nb = 0; nb < 8; nb++) {
            accO[nb][0] *= al0; accO[nb][1] *= al0;
            accO[nb][2] *= al1; accO[nb][3] *= al1;
        }

        // ---- PV: O += Ph*Vh + Ph*Vl + Pl*Vh ----
#pragma unroll
        for (int ks = 0; ks < 4; ks++) {
            float p00 = accS[2 * ks][0],     p01 = accS[2 * ks][1];
            float p02 = accS[2 * ks][2],     p03 = accS[2 * ks][3];
            float p10 = accS[2 * ks + 1][0], p11 = accS[2 * ks + 1][1];
            float p12 = accS[2 * ks + 1][2], p13 = accS[2 * ks + 1][3];
            float h00 = bf16_round(p00), h01 = bf16_round(p01);
            float h02 = bf16_round(p02), h03 = bf16_round(p03);
            float h10 = bf16_round(p10), h11 = bf16_round(p11);
            float h12 = bf16_round(p12), h13 = bf16_round(p13);
            uint32_t ph[4], pl[4];
            ph[0] = pack_bf16x2(h00, h01);
            ph[1] = pack_bf16x2(h02, h03);
            ph[2] = pack_bf16x2(h10, h11);
            ph[3] = pack_bf16x2(h12, h13);
            pl[0] = pack_bf16x2(p00 - h00, p01 - h01);
            pl[1] = pack_bf16x2(p02 - h02, p03 - h03);
            pl[2] = pack_bf16x2(p10 - h10, p11 - h11);
            pl[3] = pack_bf16x2(p12 - h12, p13 - h13);

#pragma unroll
            for (int db2 = 0; db2 < 4; db2++) {
                uint32_t addr = (uint32_t)(((ks * 16 + v_key) * FPAD
                                            + db2 * 16 + v_dof) * 2);
                uint32_t tvh[4], tvl[4];
                ldsm_x4_t(tvh, sVh_b + addr);
                ldsm_x4_t(tvl, sVl_b + addr);
                uint32_t bh0[2] = {tvh[0], tvh[1]}, bh1[2] = {tvh[2], tvh[3]};
                uint32_t bl0[2] = {tvl[0], tvl[1]}, bl1[2] = {tvl[2], tvl[3]};
                mma_bf16(accO[db2 * 2],     ph, bh0);
                mma_bf16(accO[db2 * 2 + 1], ph, bh1);
                mma_bf16(accO[db2 * 2],     ph, bl0);
                mma_bf16(accO[db2 * 2 + 1], ph, bl1);
                mma_bf16(accO[db2 * 2],     pl, bh0);
                mma_bf16(accO[db2 * 2 + 1], pl, bh1);
            }
        }
    }

    // ---- epilogue: O /= l, write pre-split ctx [B,T,E] ----
    float li0 = 1.0f / lrow0, li1 = 1.0f / lrow1;
    const int row0 = t0 + warp_m + g;
    const int row1 = row0 + 8;
#pragma unroll
    for (int nb = 0; nb < 8; nb++) {
        int d = h * HD + nb * 8 + tq * 2;
        float o0x = accO[nb][0] * li0, o0y = accO[nb][1] * li0;
        float o1x = accO[nb][2] * li1, o1y = accO[nb][3] * li1;
        size_t off0 = ((size_t)(b * TLEN + row0)) * EE + d;
        size_t off1 = ((size_t)(b * TLEN + row1)) * EE + d;
        float h0x = bf16_round(o0x), h0y = bf16_round(o0y);
        float h1x = bf16_round(o1x), h1y = bf16_round(o1y);
        *(uint32_t*)(g_cx_h + off0) = pack_bf16x2(h0x, h0y);
        *(uint32_t*)(g_cx_l + off0) = pack_bf16x2(o0x - h0x, o0y - h0y);
        *(uint32_t*)(g_cx_h + off1) = pack_bf16x2(h1x, h1y);
        *(uint32_t*)(g_cx_l + off1) = pack_bf16x2(o1x - h1x, o1y - h1y);
    }
}

// ---------------- launch ----------------------------------------------------
extern "C" void kernel_launch(void* const* d_in, const int* in_sizes, int n_in,
                              void* d_out, int out_size) {
    const float* query     = (const float*)d_in[0];
    const float* key       = (const float*)d_in[1];
    const float* value     = (const float*)d_in[2];
    const void*  mask      = d_in[3];
    const float* attn_bias = (const float*)d_in[4];
    const float* wq = (const float*)d_in[5];
    const float* bq = (const float*)d_in[6];
    const float* wk = (const float*)d_in[7];
    const float* bk = (const float*)d_in[8];
    const float* wv = (const float*)d_in[9];
    const float* bv = (const float*)d_in[10];
    const float* wo = (const float*)d_in[11];
    const float* bo = (const float*)d_in[12];
    float* out = (float*)d_out;

    unsigned short *xqh, *xql, *xkh, *xkl, *xvh, *xvl, *cxh, *cxl;
    unsigned short *wqh, *wql, *wkh, *wkl, *wvh, *wvl, *woh, *wol;
    unsigned short *qh, *ql, *kh, *kl, *vh, *vl;
    cudaGetSymbolAddress((void**)&xqh, g_xq_h); cudaGetSymbolAddress((void**)&xql, g_xq_l);
    cudaGetSymbolAddress((void**)&xkh, g_xk_h); cudaGetSymbolAddress((void**)&xkl, g_xk_l);
    cudaGetSymbolAddress((void**)&xvh, g_xv_h); cudaGetSymbolAddress((void**)&xvl, g_xv_l);
    cudaGetSymbolAddress((void**)&cxh, g_cx_h); cudaGetSymbolAddress((void**)&cxl, g_cx_l);
    cudaGetSymbolAddress((void**)&wqh, g_wq_h); cudaGetSymbolAddress((void**)&wql, g_wq_l);
    cudaGetSymbolAddress((void**)&wkh, g_wk_h); cudaGetSymbolAddress((void**)&wkl, g_wk_l);
    cudaGetSymbolAddress((void**)&wvh, g_wv_h); cudaGetSymbolAddress((void**)&wvl, g_wv_l);
    cudaGetSymbolAddress((void**)&woh, g_wo_h); cudaGetSymbolAddress((void**)&wol, g_wo_l);
    cudaGetSymbolAddress((void**)&qh, g_qh); cudaGetSymbolAddress((void**)&ql, g_ql);
    cudaGetSymbolAddress((void**)&kh, g_kh); cudaGetSymbolAddress((void**)&kl, g_kl);
    cudaGetSymbolAddress((void**)&vh, g_vh); cudaGetSymbolAddress((void**)&vl, g_vl);

    detect_mask_kernel<<<1, 256>>>((const unsigned char*)mask);
    expand_mask_kernel<<<(BB * TLEN + 255) / 256, 256>>>(mask);

    int act4 = ACT_ELEMS / 4, w4 = W_ELEMS / 4;
    split_bf16_kernel<<<(act4 + 255) / 256, 256>>>(query, xqh, xql, act4);
    split_bf16_kernel<<<(act4 + 255) / 256, 256>>>(key,   xkh, xkl, act4);
    split_bf16_kernel<<<(act4 + 255) / 256, 256>>>(value, xvh, xvl, act4);
    split_bf16_kernel<<<(w4 + 255) / 256, 256>>>(wq, wqh, wql, w4);
    split_bf16_kernel<<<(w4 + 255) / 256, 256>>>(wk, wkh, wkl, w4);
    split_bf16_kernel<<<(w4 + 255) / 256, 256>>>(wv, wvh, wvl, w4);
    split_bf16_kernel<<<(w4 + 255) / 256, 256>>>(wo, woh, wol, w4);

    // merged QKV projection
    QKVArgs args;
    args.Ah[0] = xqh; args.Al[0] = xql; args.Bh[0] = wqh; args.Bl[0] = wql;
    args.Ah[1] = xkh; args.Al[1] = xkl; args.Bh[1] = wkh; args.Bl[1] = wkl;
    args.Ah[2] = xvh; args.Al[2] = xvl; args.Bh[2] = wvh; args.Bl[2] = wvl;
    args.bias[0] = bq; args.bias[1] = bk; args.bias[2] = bv;
    args.scale[0] = SCALING; args.scale[1] = 1.0f; args.scale[2] = 1.0f;
    args.Ch[0] = qh; args.Cl[0] = ql;
    args.Ch[1] = kh; args.Cl[1] = kl;
    args.Ch[2] = vh; args.Cl[2] = vl;

    cudaFuncSetAttribute(gemm_qkv_kernel, cudaFuncAttributeMaxDynamicSharedMemorySize,
                         GSMEM);
    cudaFuncSetAttribute(gemm_out_kernel, cudaFuncAttributeMaxDynamicSharedMemorySize,
                         GSMEM);
    gemm_qkv_kernel<<<dim3(32, 8, 3), 256, GSMEM>>>(args);

    const int flash_smem = 2 * QBUF + 4 * KBUF + 64 * (int)sizeof(float);
    cudaFuncSetAttribute(flash_mma_kernel,
                         cudaFuncAttributeMaxDynamicSharedMemorySize, flash_smem);
    flash_mma_kernel<<<dim3(8, 16, 4), 256, flash_smem>>>(attn_bias);

    gemm_out_kernel<<<dim3(32, 8), 256, GSMEM>>>(cxh, cxl, woh, wol, bo, out);
}

// round 7
// speedup vs baseline: 1.1694x; 1.1694x over previous
#include <cuda_runtime.h>
#include <cuda_bf16.h>
#include <cstdint>

#define BB   4
#define TLEN 1024
#define EE   1024
#define NH   16
#define HD   64
#define SCALING 0.125f   // 64^-0.5

// ---------------- scratch (static device arrays; no runtime allocation) ----
__device__ float g_maskval[BB*TLEN];
__device__ int   g_mask_kind;

#define ACT_ELEMS (4096*1024)
#define W_ELEMS   (1024*1024)
__device__ unsigned short g_xq_h[ACT_ELEMS], g_xq_l[ACT_ELEMS];
__device__ unsigned short g_xk_h[ACT_ELEMS], g_xk_l[ACT_ELEMS];
__device__ unsigned short g_xv_h[ACT_ELEMS], g_xv_l[ACT_ELEMS];
__device__ unsigned short g_cx_h[ACT_ELEMS], g_cx_l[ACT_ELEMS];
__device__ unsigned short g_wq_h[W_ELEMS], g_wq_l[W_ELEMS];
__device__ unsigned short g_wk_h[W_ELEMS], g_wk_l[W_ELEMS];
__device__ unsigned short g_wv_h[W_ELEMS], g_wv_l[W_ELEMS];
__device__ unsigned short g_wo_h[W_ELEMS], g_wo_l[W_ELEMS];
// projected Q/K/V, pre-split bf16 hi/lo, [B,H,T,D]
__device__ unsigned short g_qh[ACT_ELEMS], g_ql[ACT_ELEMS];
__device__ unsigned short g_kh[ACT_ELEMS], g_kl[ACT_ELEMS];
__device__ unsigned short g_vh[ACT_ELEMS], g_vl[ACT_ELEMS];

// ---------------- warp-mma helpers -----------------------------------------
__device__ __forceinline__ uint32_t smem_u32(const void* p) {
    uint32_t a;
    asm("{ .reg .u64 t; cvta.to.shared.u64 t, %1; cvt.u32.u64 %0, t; }"
        : "=r"(a) : "l"(p));
    return a;
}

__device__ __forceinline__ void ldsm_x4(uint32_t r[4], uint32_t addr) {
    asm volatile("ldmatrix.sync.aligned.m8n8.x4.shared.b16 {%0,%1,%2,%3}, [%4];"
        : "=r"(r[0]), "=r"(r[1]), "=r"(r[2]), "=r"(r[3]) : "r"(addr));
}

__device__ __forceinline__ void ldsm_x4_t(uint32_t r[4], uint32_t addr) {
    asm volatile("ldmatrix.sync.aligned.m8n8.x4.trans.shared.b16 {%0,%1,%2,%3}, [%4];"
        : "=r"(r[0]), "=r"(r[1]), "=r"(r[2]), "=r"(r[3]) : "r"(addr));
}

__device__ __forceinline__ void mma_bf16(float c[4], const uint32_t a[4],
                                         const uint32_t b[2]) {
    asm volatile(
        "mma.sync.aligned.m16n8k16.row.col.f32.bf16.bf16.f32 "
        "{%0,%1,%2,%3}, {%4,%5,%6,%7}, {%8,%9}, {%0,%1,%2,%3};"
        : "+f"(c[0]), "+f"(c[1]), "+f"(c[2]), "+f"(c[3])
        : "r"(a[0]), "r"(a[1]), "r"(a[2]), "r"(a[3]), "r"(b[0]), "r"(b[1]));
}

__device__ __forceinline__ uint32_t pack_bf16x2(float lo, float hi) {
    uint32_t r;
    asm("cvt.rn.bf16x2.f32 %0, %1, %2;" : "=r"(r) : "f"(hi), "f"(lo));
    return r;
}

__device__ __forceinline__ float bf16_round(float x) {
    return __bfloat162float(__float2bfloat16_rn(x));
}

__device__ __forceinline__ void cp_async16(uint32_t smem_addr, const void* gptr) {
    asm volatile("cp.async.cg.shared.global [%0], [%1], 16;"
        :: "r"(smem_addr), "l"(gptr));
}
#define CP_COMMIT() asm volatile("cp.async.commit_group;" ::: "memory")
#define CP_WAIT(n)  asm volatile("cp.async.wait_group %0;" :: "n"(n) : "memory")

// ---------------- mask dtype sniffing --------------------------------------
__global__ void detect_mask_kernel(const unsigned char* __restrict__ p) {
    __shared__ int c0s, c1s;
    if (threadIdx.x == 0) { c0s = 0; c1s = 0; }
    __syncthreads();
    int c0 = 0, c1 = 0;
    for (int i = threadIdx.x; i < 1024; i += blockDim.x) {
        if (p[4 * i + 1]) c1++;
        if (p[4 * i + 0]) c0++;
    }
    if (c0) atomicAdd(&c0s, c0);
    if (c1) atomicAdd(&c1s, c1);
    __syncthreads();
    if (threadIdx.x == 0) g_mask_kind = c1s ? 1 : (c0s ? 0 : 2);
}

__global__ void expand_mask_kernel(const void* __restrict__ p) {
    int i = blockIdx.x * blockDim.x + threadIdx.x;
    if (i >= BB * TLEN) return;
    int kind = g_mask_kind;
    bool m;
    if (kind == 1)      m = ((const unsigned char*)p)[i] != 0;
    else if (kind == 0) m = ((const int*)p)[i] != 0;
    else                m = ((const float*)p)[i] != 0.0f;
    g_maskval[i] = m ? -1e30f : 0.0f;
}

// ---------------- fp32 -> bf16 hi/lo split (z-batched) ----------------------
struct SplitArgs {
    const float* src[4];
    unsigned short* hi[4];
    unsigned short* lo[4];
    int n4;
};

__global__ void split_multi_kernel(SplitArgs a) {
    int i = blockIdx.x * blockDim.x + threadIdx.x;
    if (i >= a.n4) return;
    int z = blockIdx.z;
    const float* src = a.src[z];
    unsigned short* hi = a.hi[z];
    unsigned short* lo = a.lo[z];
    float4 v = ((const float4*)src)[i];
    float vv[4] = {v.x, v.y, v.z, v.w};
    unsigned short h[4], l[4];
#pragma unroll
    for (int j = 0; j < 4; j++) {
        __nv_bfloat16 bh = __float2bfloat16_rn(vv[j]);
        float r = vv[j] - __bfloat162float(bh);
        h[j] = __bfloat16_as_ushort(bh);
        l[j] = __bfloat16_as_ushort(__float2bfloat16_rn(r));
    }
    uint2 ph, pl;
    ph.x = (uint32_t)h[0] | ((uint32_t)h[1] << 16);
    ph.y = (uint32_t)h[2] | ((uint32_t)h[3] << 16);
    pl.x = (uint32_t)l[0] | ((uint32_t)l[1] << 16);
    pl.y = (uint32_t)l[2] | ((uint32_t)l[3] << 16);
    *(uint2*)(hi + 4 * (size_t)i) = ph;
    *(uint2*)(lo + 4 * (size_t)i) = pl;
}

// ---------------- cp.async double-buffered split-bf16 GEMM core -------------
#define GSTR 24
#define GBUF (128 * GSTR * 2)        // 6144 B per operand buffer
#define GSTAGE (4 * GBUF)            // 24576 B per stage
#define GSMEM (2 * GSTAGE)           // 49152 B total

struct QKVArgs {
    const unsigned short *Ah[3], *Al[3], *Bh[3], *Bl[3];
    const float* bias[3];
    float scale[3];
    unsigned short *Ch[3], *Cl[3];
};

__device__ __forceinline__ void gemm_body(
    const unsigned short* __restrict__ Ah, const unsigned short* __restrict__ Al,
    const unsigned short* __restrict__ Bh, const unsigned short* __restrict__ Bl,
    char* smem, int m0, int n0, float acc[2][8][4])
{
    const int tid = threadIdx.x, wid = tid >> 5, lane = tid & 31;
    const int warp_m = (wid & 3) * 32;
    const int warp_n = (wid >> 2) * 64;
    const uint32_t sbase = smem_u32(smem);

    const int cp_r = tid >> 1, cp_half = tid & 1;
    const uint32_t cp_soff = (uint32_t)(cp_r * (GSTR * 2) + cp_half * 16);
    const size_t cp_gA = (size_t)(m0 + cp_r) * 1024 + cp_half * 8;
    const size_t cp_gB = (size_t)(n0 + cp_r) * 1024 + cp_half * 8;

    const int a_row = warp_m + (lane & 15);
    const int a_csel = (lane >> 4) << 3;
    const int b_row = warp_n + ((lane >> 4) << 3) + (lane & 7);
    const int b_csel = ((lane >> 3) & 1) << 3;

#pragma unroll
    for (int mb = 0; mb < 2; mb++)
#pragma unroll
        for (int nb = 0; nb < 8; nb++)
#pragma unroll
            for (int q = 0; q < 4; q++) acc[mb][nb][q] = 0.0f;

    auto issue = [&](int kc) {
        uint32_t st = sbase + (kc & 1) * GSTAGE;
        size_t kofs = (size_t)kc * 16;
        cp_async16(st + 0 * GBUF + cp_soff, Ah + cp_gA + kofs);
        cp_async16(st + 1 * GBUF + cp_soff, Al + cp_gA + kofs);
        cp_async16(st + 2 * GBUF + cp_soff, Bh + cp_gB + kofs);
        cp_async16(st + 3 * GBUF + cp_soff, Bl + cp_gB + kofs);
        CP_COMMIT();
    };

    issue(0);
    for (int kc = 0; kc < 64; kc++) {
        if (kc + 1 < 64) { issue(kc + 1); CP_WAIT(1); }
        else             { CP_WAIT(0); }
        __syncthreads();

        const uint32_t st = sbase + (kc & 1) * GSTAGE;
        uint32_t afh[2][4], afl[2][4];
#pragma unroll
        for (int mb = 0; mb < 2; mb++) {
            uint32_t off = (uint32_t)(((a_row + mb * 16) * GSTR + a_csel) * 2);
            ldsm_x4(afh[mb], st + 0 * GBUF + off);
            ldsm_x4(afl[mb], st + 1 * GBUF + off);
        }
#pragma unroll
        for (int nb2 = 0; nb2 < 4; nb2++) {
            uint32_t off = (uint32_t)(((b_row + nb2 * 16) * GSTR + b_csel) * 2);
            uint32_t th[4], tl[4];
            ldsm_x4(th, st + 2 * GBUF + off);
            ldsm_x4(tl, st + 3 * GBUF + off);
            uint32_t bh0[2] = {th[0], th[1]}, bh1[2] = {th[2], th[3]};
            uint32_t bl0[2] = {tl[0], tl[1]}, bl1[2] = {tl[2], tl[3]};
#pragma unroll
            for (int mb = 0; mb < 2; mb++) {
                mma_bf16(acc[mb][nb2 * 2],     afh[mb], bh0);
                mma_bf16(acc[mb][nb2 * 2 + 1], afh[mb], bh1);
                mma_bf16(acc[mb][nb2 * 2],     afh[mb], bl0);
                mma_bf16(acc[mb][nb2 * 2 + 1], afh[mb], bl1);
                mma_bf16(acc[mb][nb2 * 2],     afl[mb], bh0);
                mma_bf16(acc[mb][nb2 * 2 + 1], afl[mb], bh1);
            }
        }
        __syncthreads();
    }
}

// merged QKV projection: grid (32, 8, 3), output pre-split [B,H,T,D]
__global__ void __launch_bounds__(256, 2) gemm_qkv_kernel(QKVArgs args)
{
    extern __shared__ char smem[];
    const int z = blockIdx.z;
    const int tid = threadIdx.x, wid = tid >> 5, lane = tid & 31;
    const int m0 = blockIdx.x * 128, n0 = blockIdx.y * 128;

    float acc[2][8][4];
    gemm_body(args.Ah[z], args.Al[z], args.Bh[z], args.Bl[z], smem, m0, n0, acc);

    const float scale = args.scale[z];
    const float* bias = args.bias[z];
    unsigned short* Ch = args.Ch[z];
    unsigned short* Cl = args.Cl[z];
    const int warp_m = (wid & 3) * 32;
    const int warp_n = (wid >> 2) * 64;
    const int g = lane >> 2, tg = lane & 3;
#pragma unroll
    for (int mb = 0; mb < 2; mb++) {
#pragma unroll
        for (int nb = 0; nb < 8; nb++) {
            int n = n0 + warp_n + nb * 8 + tg * 2;
            float b0 = bias[n], b1 = bias[n + 1];
#pragma unroll
            for (int half = 0; half < 2; half++) {
                int m = m0 + warp_m + mb * 16 + g + half * 8;
                float vx = (acc[mb][nb][half * 2 + 0] + b0) * scale;
                float vy = (acc[mb][nb][half * 2 + 1] + b1) * scale;
                int bb = m >> 10, t = m & 1023, hh = n >> 6, d = n & 63;
                size_t off = (((size_t)(bb * NH + hh)) * TLEN + t) * HD + d;
                float hx = bf16_round(vx), hy = bf16_round(vy);
                *(uint32_t*)(Ch + off) = pack_bf16x2(hx, hy);
                *(uint32_t*)(Cl + off) = pack_bf16x2(vx - hx, vy - hy);
            }
        }
    }
}

// output projection: fp32 out [M,N]
__global__ void __launch_bounds__(256, 2) gemm_out_kernel(
    const unsigned short* __restrict__ Ah, const unsigned short* __restrict__ Al,
    const unsigned short* __restrict__ Bh, const unsigned short* __restrict__ Bl,
    const float* __restrict__ bias, float* __restrict__ Cf)
{
    extern __shared__ char smem[];
    const int tid = threadIdx.x, wid = tid >> 5, lane = tid & 31;
    const int m0 = blockIdx.x * 128, n0 = blockIdx.y * 128;

    float acc[2][8][4];
    gemm_body(Ah, Al, Bh, Bl, smem, m0, n0, acc);

    const int warp_m = (wid & 3) * 32;
    const int warp_n = (wid >> 2) * 64;
    const int g = lane >> 2, tg = lane & 3;
#pragma unroll
    for (int mb = 0; mb < 2; mb++) {
#pragma unroll
        for (int nb = 0; nb < 8; nb++) {
            int n = n0 + warp_n + nb * 8 + tg * 2;
            float b0 = bias[n], b1 = bias[n + 1];
#pragma unroll
            for (int half = 0; half < 2; half++) {
                int m = m0 + warp_m + mb * 16 + g + half * 8;
                float2 v;
                v.x = acc[mb][nb][half * 2 + 0] + b0;
                v.y = acc[mb][nb][half * 2 + 1] + b1;
                *(float2*)(Cf + (size_t)m * 1024 + n) = v;
            }
        }
    }
}

// ---------------- tensor-core flash attention (64-row tiles, K/V dbl-buf) ---
// CTA: 128 threads (4 warps), 64 query rows. Grid (16,16,4).
// smem: 8 buffers of FBUF bytes + mask.
//   bufs 0-3: K/V stage parity 0 (Kh,Kl,Vh,Vl); bufs 4-7: stage parity 1.
//   Q initially lives in bufs 4,5 (consumed into fragments before stage 1 lands).
#define FPAD 72
#define FBUF (64 * FPAD * 2)   // 9216 bytes

__global__ void __launch_bounds__(128) flash_mma_kernel(
    const float* __restrict__ attn_bias)
{
    extern __shared__ char sm[];
    float* smask = (float*)(sm + 8 * FBUF);

    const int tid = threadIdx.x, wid = tid >> 5, lane = tid & 31;
    const int t0 = blockIdx.x * 64, h = blockIdx.y, b = blockIdx.z;
    const int bh = b * NH + h;
    const size_t base = (size_t)bh * TLEN * HD;
    const unsigned short *qh_g = g_qh + base, *ql_g = g_ql + base;
    const unsigned short *kh_g = g_kh + base, *kl_g = g_kl + base;
    const unsigned short *vh_g = g_vh + base, *vl_g = g_vl + base;
    const float* biasbase = attn_bias + (size_t)bh * TLEN * TLEN;

    const int warp_m = wid * 16;
    const int g = lane >> 2, tq = lane & 3;
    const uint32_t sb = smem_u32(sm);

    // issue K/V tile loads for step via cp.async (one commit group)
    auto issue_kv = [&](int step) {
        uint32_t bufs = sb + ((step & 1) ? 4u : 0u) * FBUF;
        int s0 = step * 64;
#pragma unroll
        for (int rep = 0; rep < 4; rep++) {
            int i = rep * 128 + tid;
            int r = i >> 3, c8 = (i & 7) << 3;
            uint32_t so = (uint32_t)(r * (FPAD * 2) + c8 * 2);
            size_t go = (size_t)(s0 + r) * HD + c8;
            cp_async16(bufs + 0 * FBUF + so, kh_g + go);
            cp_async16(bufs + 1 * FBUF + so, kl_g + go);
            cp_async16(bufs + 2 * FBUF + so, vh_g + go);
            cp_async16(bufs + 3 * FBUF + so, vl_g + go);
        }
        CP_COMMIT();
    };

    // stage 0 K/V starts immediately
    issue_kv(0);

    // Q into bufs 4,5 (regular stores)
    unsigned short* sQh = (unsigned short*)(sm + 4 * FBUF);
    unsigned short* sQl = (unsigned short*)(sm + 5 * FBUF);
    for (int i = tid; i < 1024; i += 128) {
        int r = i >> 4, c4 = (i & 15) << 2;
        size_t go = (size_t)(t0 + r) * HD + c4;
        *(uint2*)&sQh[r * FPAD + c4] = *(const uint2*)(qh_g + go);
        *(uint2*)&sQl[r * FPAD + c4] = *(const uint2*)(ql_g + go);
    }
    __syncthreads();

    const int a_row = warp_m + (lane & 15);
    const int a_csel = (lane >> 4) << 3;
    uint32_t qh[4][4], ql[4][4];
#pragma unroll
    for (int kk = 0; kk < 4; kk++) {
        uint32_t off = (uint32_t)((a_row * FPAD + kk * 16 + a_csel) * 2);
        ldsm_x4(qh[kk], sb + 4 * FBUF + off);
        ldsm_x4(ql[kk], sb + 5 * FBUF + off);
    }
    __syncthreads();   // all warps have Q fragments; bufs 4-7 reusable

    issue_kv(1);       // stage 1 overwrites Q area

    float accO[8][4];
#pragma unroll
    for (int nb = 0; nb < 8; nb++)
#pragma unroll
        for (int q = 0; q < 4; q++) accO[nb][q] = 0.0f;
    float mrow0 = -1e30f, mrow1 = -1e30f, lrow0 = 0.0f, lrow1 = 0.0f;

    const int b_rowbase = ((lane >> 4) << 3) + (lane & 7);
    const int b_csel = ((lane >> 3) & 1) << 3;
    const int v_key = (((lane >> 3) & 1) << 3) + (lane & 7);
    const int v_dof = (lane >> 4) << 3;

    for (int it = 0; it < 16; it++) {
        const int s0 = it * 64;
        if (it < 15) { CP_WAIT(1); } else { CP_WAIT(0); }
        if (tid < 64) smask[tid] = g_maskval[b * TLEN + s0 + tid];
        __syncthreads();

        const uint32_t bufs = sb + ((it & 1) ? 4u : 0u) * FBUF;
        const uint32_t kh_b = bufs, kl_b = bufs + FBUF;
        const uint32_t vh_b = bufs + 2 * FBUF, vl_b = bufs + 3 * FBUF;

        // ---- S = Qh*Kh + Qh*Kl + Ql*Kh ----
        float accS[8][4];
#pragma unroll
        for (int nb = 0; nb < 8; nb++)
#pragma unroll
            for (int q = 0; q < 4; q++) accS[nb][q] = 0.0f;

#pragma unroll
        for (int kk = 0; kk < 4; kk++) {
#pragma unroll
            for (int nb2 = 0; nb2 < 4; nb2++) {
                uint32_t off = (uint32_t)(((b_rowbase + nb2 * 16) * FPAD + kk * 16 + b_csel) * 2);
                uint32_t th[4], tl[4];
                ldsm_x4(th, kh_b + off);
                ldsm_x4(tl, kl_b + off);
                uint32_t bh0[2] = {th[0], th[1]}, bh1[2] = {th[2], th[3]};
                uint32_t bl0[2] = {tl[0], tl[1]}, bl1[2] = {tl[2], tl[3]};
                mma_bf16(accS[nb2 * 2],     qh[kk], bh0);
                mma_bf16(accS[nb2 * 2 + 1], qh[kk], bh1);
                mma_bf16(accS[nb2 * 2],     qh[kk], bl0);
                mma_bf16(accS[nb2 * 2 + 1], qh[kk], bl1);
                mma_bf16(accS[nb2 * 2],     ql[kk], bh0);
                mma_bf16(accS[nb2 * 2 + 1], ql[kk], bh1);
            }
        }

        // ---- add bias + mask ----
        const int row0 = t0 + warp_m + g;
        const int row1 = row0 + 8;
#pragma unroll
        for (int nb = 0; nb < 8; nb++) {
            int col = s0 + nb * 8 + tq * 2;
            float2 bv0 = *(const float2*)(biasbase + (size_t)row0 * TLEN + col);
            float2 bv1 = *(const float2*)(biasbase + (size_t)row1 * TLEN + col);
            float mk0 = smask[nb * 8 + tq * 2];
            float mk1 = smask[nb * 8 + tq * 2 + 1];
            accS[nb][0] += bv0.x + mk0;
            accS[nb][1] += bv0.y + mk1;
            accS[nb][2] += bv1.x + mk0;
            accS[nb][3] += bv1.y + mk1;
        }

        // ---- online softmax (quad reductions) ----
        float mx0 = mrow0, mx1 = mrow1;
#pragma unroll
        for (int nb = 0; nb < 8; nb++) {
            mx0 = fmaxf(mx0, fmaxf(accS[nb][0], accS[nb][1]));
            mx1 = fmaxf(mx1, fmaxf(accS[nb][2], accS[nb][3]));
        }
        mx0 = fmaxf(mx0, __shfl_xor_sync(0xFFFFFFFF, mx0, 1));
        mx0 = fmaxf(mx0, __shfl_xor_sync(0xFFFFFFFF, mx0, 2));
        mx1 = fmaxf(mx1, __shfl_xor_sync(0xFFFFFFFF, mx1, 1));
        mx1 = fmaxf(mx1, __shfl_xor_sync(0xFFFFFFFF, mx1, 2));
        float al0 = __expf(mrow0 - mx0), al1 = __expf(mrow1 - mx1);
        mrow0 = mx0; mrow1 = mx1;

        float sum0 = 0.0f, sum1 = 0.0f;
#pragma unroll
        for (int nb = 0; nb < 8; nb++) {
            accS[nb][0] = __expf(accS[nb][0] - mx0);
            accS[nb][1] = __expf(accS[nb][1] - mx0);
            accS[nb][2] = __expf(accS[nb][2] - mx1);
            accS[nb][3] = __expf(accS[nb][3] - mx1);
            sum0 += accS[nb][0] + accS[nb][1];
            sum1 += accS[nb][2] + accS[nb][3];
        }
        sum0 += __shfl_xor_sync(0xFFFFFFFF, sum0, 1);
        sum0 += __shfl_xor_sync(0xFFFFFFFF, sum0, 2);
        sum1 += __shfl_xor_sync(0xFFFFFFFF, sum1, 1);
        sum1 += __shfl_xor_sync(0xFFFFFFFF, sum1, 2);
        lrow0 = lrow0 * al0 + sum0;
        lrow1 = lrow1 * al1 + sum1;

#pragma unroll
        for (int nb = 0; nb < 8; nb++) {
            accO[nb][0] *= al0; accO[nb][1] *= al0;
            accO[nb][2] *= al1; accO[nb][3] *= al1;
        }

        // ---- PV: O += Ph*Vh + Ph*Vl + Pl*Vh ----
#pragma unroll
        for (int ks = 0; ks < 4; ks++) {
            float p00 = accS[2 * ks][0],     p01 = accS[2 * ks][1];
            float p02 = accS[2 * ks][2],     p03 = accS[2 * ks][3];
            float p10 = accS[2 * ks + 1][0], p11 = accS[2 * ks + 1][1];
            float p12 = accS[2 * ks + 1][2], p13 = accS[2 * ks + 1][3];
            float h00 = bf16_round(p00), h01 = bf16_round(p01);
            float h02 = bf16_round(p02), h03 = bf16_round(p03);
            float h10 = bf16_round(p10), h11 = bf16_round(p11);
            float h12 = bf16_round(p12), h13 = bf16_round(p13);
            uint32_t ph[4], pl[4];
            ph[0] = pack_bf16x2(h00, h01);
            ph[1] = pack_bf16x2(h02, h03);
            ph[2] = pack_bf16x2(h10, h11);
            ph[3] = pack_bf16x2(h12, h13);
            pl[0] = pack_bf16x2(p00 - h00, p01 - h01);
            pl[1] = pack_bf16x2(p02 - h02, p03 - h03);
            pl[2] = pack_bf16x2(p10 - h10, p11 - h11);
            pl[3] = pack_bf16x2(p12 - h12, p13 - h13);

#pragma unroll
            for (int db2 = 0; db2 < 4; db2++) {
                uint32_t addr = (uint32_t)(((ks * 16 + v_key) * FPAD
                                            + db2 * 16 + v_dof) * 2);
                uint32_t tvh[4], tvl[4];
                ldsm_x4_t(tvh, vh_b + addr);
                ldsm_x4_t(tvl, vl_b + addr);
                uint32_t bh0[2] = {tvh[0], tvh[1]}, bh1[2] = {tvh[2], tvh[3]};
                uint32_t bl0[2] = {tvl[0], tvl[1]}, bl1[2] = {tvl[2], tvl[3]};
                mma_bf16(accO[db2 * 2],     ph, bh0);
                mma_bf16(accO[db2 * 2 + 1], ph, bh1);
                mma_bf16(accO[db2 * 2],     ph, bl0);
                mma_bf16(accO[db2 * 2 + 1], ph, bl1);
                mma_bf16(accO[db2 * 2],     pl, bh0);
                mma_bf16(accO[db2 * 2 + 1], pl, bh1);
            }
        }

        __syncthreads();                   // all warps done reading this stage
        if (it + 2 < 16) issue_kv(it + 2); // refill the buffers just freed
    }

    // ---- epilogue: O /= l, write pre-split ctx [B,T,E] ----
    float li0 = 1.0f / lrow0, li1 = 1.0f / lrow1;
    const int row0 = t0 + warp_m + g;
    const int row1 = row0 + 8;
#pragma unroll
    for (int nb = 0; nb < 8; nb++) {
        int d = h * HD + nb * 8 + tq * 2;
        float o0x = accO[nb][0] * li0, o0y = accO[nb][1] * li0;
        float o1x = accO[nb][2] * li1, o1y = accO[nb][3] * li1;
        size_t off0 = ((size_t)(b * TLEN + row0)) * EE + d;
        size_t off1 = ((size_t)(b * TLEN + row1)) * EE + d;
        float h0x = bf16_round(o0x), h0y = bf16_round(o0y);
        float h1x = bf16_round(o1x), h1y = bf16_round(o1y);
        *(uint32_t*)(g_cx_h + off0) = pack_bf16x2(h0x, h0y);
        *(uint32_t*)(g_cx_l + off0) = pack_bf16x2(o0x - h0x, o0y - h0y);
        *(uint32_t*)(g_cx_h + off1) = pack_bf16x2(h1x, h1y);
        *(uint32_t*)(g_cx_l + off1) = pack_bf16x2(o1x - h1x, o1y - h1y);
    }
}

// ---------------- launch ----------------------------------------------------
extern "C" void kernel_launch(void* const* d_in, const int* in_sizes, int n_in,
                              void* d_out, int out_size) {
    const float* query     = (const float*)d_in[0];
    const float* key       = (const float*)d_in[1];
    const float* value     = (const float*)d_in[2];
    const void*  mask      = d_in[3];
    const float* attn_bias = (const float*)d_in[4];
    const float* wq = (const float*)d_in[5];
    const float* bq = (const float*)d_in[6];
    const float* wk = (const float*)d_in[7];
    const float* bk = (const float*)d_in[8];
    const float* wv = (const float*)d_in[9];
    const float* bv = (const float*)d_in[10];
    const float* wo = (const float*)d_in[11];
    const float* bo = (const float*)d_in[12];
    float* out = (float*)d_out;

    unsigned short *xqh, *xql, *xkh, *xkl, *xvh, *xvl, *cxh, *cxl;
    unsigned short *wqh, *wql, *wkh, *wkl, *wvh, *wvl, *woh, *wol;
    unsigned short *qh, *ql, *kh, *kl, *vh, *vl;
    cudaGetSymbolAddress((void**)&xqh, g_xq_h); cudaGetSymbolAddress((void**)&xql, g_xq_l);
    cudaGetSymbolAddress((void**)&xkh, g_xk_h); cudaGetSymbolAddress((void**)&xkl, g_xk_l);
    cudaGetSymbolAddress((void**)&xvh, g_xv_h); cudaGetSymbolAddress((void**)&xvl, g_xv_l);
    cudaGetSymbolAddress((void**)&cxh, g_cx_h); cudaGetSymbolAddress((void**)&cxl, g_cx_l);
    cudaGetSymbolAddress((void**)&wqh, g_wq_h); cudaGetSymbolAddress((void**)&wql, g_wq_l);
    cudaGetSymbolAddress((void**)&wkh, g_wk_h); cudaGetSymbolAddress((void**)&wkl, g_wk_l);
    cudaGetSymbolAddress((void**)&wvh, g_wv_h); cudaGetSymbolAddress((void**)&wvl, g_wv_l);
    cudaGetSymbolAddress((void**)&woh, g_wo_h); cudaGetSymbolAddress((void**)&wol, g_wo_l);
    cudaGetSymbolAddress((void**)&qh, g_qh); cudaGetSymbolAddress((void**)&ql, g_ql);
    cudaGetSymbolAddress((void**)&kh, g_kh); cudaGetSymbolAddress((void**)&kl, g_kl);
    cudaGetSymbolAddress((void**)&vh, g_vh); cudaGetSymbolAddress((void**)&vl, g_vl);

    detect_mask_kernel<<<1, 256>>>((const unsigned char*)mask);
    expand_mask_kernel<<<(BB * TLEN + 255) / 256, 256>>>(mask);

    int act4 = ACT_ELEMS / 4, w4 = W_ELEMS / 4;

    SplitArgs sa;
    sa.src[0] = query; sa.hi[0] = xqh; sa.lo[0] = xql;
    sa.src[1] = key;   sa.hi[1] = xkh; sa.lo[1] = xkl;
    sa.src[2] = value; sa.hi[2] = xvh; sa.lo[2] = xvl;
    sa.src[3] = query; sa.hi[3] = xqh; sa.lo[3] = xql;  // unused for acts
    sa.n4 = act4;
    split_multi_kernel<<<dim3((act4 + 255) / 256, 1, 3), 256>>>(sa);

    SplitArgs sw;
    sw.src[0] = wq; sw.hi[0] = wqh; sw.lo[0] = wql;
    sw.src[1] = wk; sw.hi[1] = wkh; sw.lo[1] = wkl;
    sw.src[2] = wv; sw.hi[2] = wvh; sw.lo[2] = wvl;
    sw.src[3] = wo; sw.hi[3] = woh; sw.lo[3] = wol;
    sw.n4 = w4;
    split_multi_kernel<<<dim3((w4 + 255) / 256, 1, 4), 256>>>(sw);

    QKVArgs args;
    args.Ah[0] = xqh; args.Al[0] = xql; args.Bh[0] = wqh; args.Bl[0] = wql;
    args.Ah[1] = xkh; args.Al[1] = xkl; args.Bh[1] = wkh; args.Bl[1] = wkl;
    args.Ah[2] = xvh; args.Al[2] = xvl; args.Bh[2] = wvh; args.Bl[2] = wvl;
    args.bias[0] = bq; args.bias[1] = bk; args.bias[2] = bv;
    args.scale[0] = SCALING; args.scale[1] = 1.0f; args.scale[2] = 1.0f;
    args.Ch[0] = qh; args.Cl[0] = ql;
    args.Ch[1] = kh; args.Cl[1] = kl;
    args.Ch[2] = vh; args.Cl[2] = vl;

    cudaFuncSetAttribute(gemm_qkv_kernel, cudaFuncAttributeMaxDynamicSharedMemorySize,
                         GSMEM);
    cudaFuncSetAttribute(gemm_out_kernel, cudaFuncAttributeMaxDynamicSharedMemorySize,
                         GSMEM);
    gemm_qkv_kernel<<<dim3(32, 8, 3), 256, GSMEM>>>(args);

    const int flash_smem = 8 * FBUF + 64 * (int)sizeof(float);
    cudaFuncSetAttribute(flash_mma_kernel,
                         cudaFuncAttributeMaxDynamicSharedMemorySize, flash_smem);
    flash_mma_kernel<<<dim3(16, 16, 4), 128, flash_smem>>>(attn_bias);

    gemm_out_kernel<<<dim3(32, 8), 256, GSMEM>>>(cxh, cxl, woh, wol, bo, out);
}

// round 8
// speedup vs baseline: 1.2630x; 1.0800x over previous
#include <cuda_runtime.h>
#include <cuda_bf16.h>
#include <cstdint>

#define BB   4
#define TLEN 1024
#define EE   1024
#define NH   16
#define HD   64
#define SCALING 0.125f   // 64^-0.5

// ---------------- scratch (static device arrays; no runtime allocation) ----
__device__ float g_maskval[BB*TLEN];
__device__ int   g_mask_kind;

#define ACT_ELEMS (4096*1024)
#define W_ELEMS   (1024*1024)
__device__ unsigned short g_xq_h[ACT_ELEMS], g_xq_l[ACT_ELEMS];
__device__ unsigned short g_xk_h[ACT_ELEMS], g_xk_l[ACT_ELEMS];
__device__ unsigned short g_xv_h[ACT_ELEMS], g_xv_l[ACT_ELEMS];
__device__ unsigned short g_cx_h[ACT_ELEMS], g_cx_l[ACT_ELEMS];
__device__ unsigned short g_wq_h[W_ELEMS], g_wq_l[W_ELEMS];
__device__ unsigned short g_wk_h[W_ELEMS], g_wk_l[W_ELEMS];
__device__ unsigned short g_wv_h[W_ELEMS], g_wv_l[W_ELEMS];
__device__ unsigned short g_wo_h[W_ELEMS], g_wo_l[W_ELEMS];
// projected Q/K/V, pre-split bf16 hi/lo, [B,H,T,D]
__device__ unsigned short g_qh[ACT_ELEMS], g_ql[ACT_ELEMS];
__device__ unsigned short g_kh[ACT_ELEMS], g_kl[ACT_ELEMS];
__device__ unsigned short g_vh[ACT_ELEMS], g_vl[ACT_ELEMS];

// ---------------- warp-mma helpers -----------------------------------------
__device__ __forceinline__ uint32_t smem_u32(const void* p) {
    uint32_t a;
    asm("{ .reg .u64 t; cvta.to.shared.u64 t, %1; cvt.u32.u64 %0, t; }"
        : "=r"(a) : "l"(p));
    return a;
}

__device__ __forceinline__ void ldsm_x4(uint32_t r[4], uint32_t addr) {
    asm volatile("ldmatrix.sync.aligned.m8n8.x4.shared.b16 {%0,%1,%2,%3}, [%4];"
        : "=r"(r[0]), "=r"(r[1]), "=r"(r[2]), "=r"(r[3]) : "r"(addr));
}

__device__ __forceinline__ void ldsm_x4_t(uint32_t r[4], uint32_t addr) {
    asm volatile("ldmatrix.sync.aligned.m8n8.x4.trans.shared.b16 {%0,%1,%2,%3}, [%4];"
        : "=r"(r[0]), "=r"(r[1]), "=r"(r[2]), "=r"(r[3]) : "r"(addr));
}

__device__ __forceinline__ void mma_bf16(float c[4], const uint32_t a[4],
                                         const uint32_t b[2]) {
    asm volatile(
        "mma.sync.aligned.m16n8k16.row.col.f32.bf16.bf16.f32 "
        "{%0,%1,%2,%3}, {%4,%5,%6,%7}, {%8,%9}, {%0,%1,%2,%3};"
        : "+f"(c[0]), "+f"(c[1]), "+f"(c[2]), "+f"(c[3])
        : "r"(a[0]), "r"(a[1]), "r"(a[2]), "r"(a[3]), "r"(b[0]), "r"(b[1]));
}

__device__ __forceinline__ uint32_t pack_bf16x2(float lo, float hi) {
    uint32_t r;
    asm("cvt.rn.bf16x2.f32 %0, %1, %2;" : "=r"(r) : "f"(hi), "f"(lo));
    return r;
}

__device__ __forceinline__ float bf16_round(float x) {
    return __bfloat162float(__float2bfloat16_rn(x));
}

__device__ __forceinline__ void cp_async16(uint32_t smem_addr, const void* gptr) {
    asm volatile("cp.async.cg.shared.global [%0], [%1], 16;"
        :: "r"(smem_addr), "l"(gptr));
}
#define CP_COMMIT() asm volatile("cp.async.commit_group;" ::: "memory")
#define CP_WAIT(n)  asm volatile("cp.async.wait_group %0;" :: "n"(n) : "memory")

// ---------------- mask dtype sniffing --------------------------------------
__global__ void detect_mask_kernel(const unsigned char* __restrict__ p) {
    __shared__ int c0s, c1s;
    if (threadIdx.x == 0) { c0s = 0; c1s = 0; }
    __syncthreads();
    int c0 = 0, c1 = 0;
    for (int i = threadIdx.x; i < 1024; i += blockDim.x) {
        if (p[4 * i + 1]) c1++;
        if (p[4 * i + 0]) c0++;
    }
    if (c0) atomicAdd(&c0s, c0);
    if (c1) atomicAdd(&c1s, c1);
    __syncthreads();
    if (threadIdx.x == 0) g_mask_kind = c1s ? 1 : (c0s ? 0 : 2);
}

__global__ void expand_mask_kernel(const void* __restrict__ p) {
    int i = blockIdx.x * blockDim.x + threadIdx.x;
    if (i >= BB * TLEN) return;
    int kind = g_mask_kind;
    bool m;
    if (kind == 1)      m = ((const unsigned char*)p)[i] != 0;
    else if (kind == 0) m = ((const int*)p)[i] != 0;
    else                m = ((const float*)p)[i] != 0.0f;
    g_maskval[i] = m ? -1e30f : 0.0f;
}

// ---------------- fp32 -> bf16 hi/lo split (z-batched) ----------------------
struct SplitArgs {
    const float* src[4];
    unsigned short* hi[4];
    unsigned short* lo[4];
    int n4;
};

__global__ void split_multi_kernel(SplitArgs a) {
    int i = blockIdx.x * blockDim.x + threadIdx.x;
    if (i >= a.n4) return;
    int z = blockIdx.z;
    const float* src = a.src[z];
    unsigned short* hi = a.hi[z];
    unsigned short* lo = a.lo[z];
    float4 v = ((const float4*)src)[i];
    float vv[4] = {v.x, v.y, v.z, v.w};
    unsigned short h[4], l[4];
#pragma unroll
    for (int j = 0; j < 4; j++) {
        __nv_bfloat16 bh = __float2bfloat16_rn(vv[j]);
        float r = vv[j] - __bfloat162float(bh);
        h[j] = __bfloat16_as_ushort(bh);
        l[j] = __bfloat16_as_ushort(__float2bfloat16_rn(r));
    }
    uint2 ph, pl;
    ph.x = (uint32_t)h[0] | ((uint32_t)h[1] << 16);
    ph.y = (uint32_t)h[2] | ((uint32_t)h[3] << 16);
    pl.x = (uint32_t)l[0] | ((uint32_t)l[1] << 16);
    pl.y = (uint32_t)l[2] | ((uint32_t)l[3] << 16);
    *(uint2*)(hi + 4 * (size_t)i) = ph;
    *(uint2*)(lo + 4 * (size_t)i) = pl;
}

// ---------------- cp.async 3-stage split-bf16 GEMM --------------------------
// C = (A @ B^T + bias) * scale.  M=4096, N=1024, K=1024.
// CTA tile 128x128, k-chunk 16, 3 smem stages, ONE sync per chunk.
#define GSTR 24
#define GBUF (128 * GSTR * 2)        // 6144 B per operand buffer
#define GSTAGE (4 * GBUF)            // 24576 B per stage
#define GSMEM (3 * GSTAGE)           // 73728 B total

__device__ __forceinline__ void gemm_body(
    const unsigned short* __restrict__ Ah, const unsigned short* __restrict__ Al,
    const unsigned short* __restrict__ Bh, const unsigned short* __restrict__ Bl,
    char* smem, int m0, int n0, float acc[2][8][4])
{
    const int tid = threadIdx.x, wid = tid >> 5, lane = tid & 31;
    const int warp_m = (wid & 3) * 32;
    const int warp_n = (wid >> 2) * 64;
    const uint32_t sbase = smem_u32(smem);

    const int cp_r = tid >> 1, cp_half = tid & 1;
    const uint32_t cp_soff = (uint32_t)(cp_r * (GSTR * 2) + cp_half * 16);
    const size_t cp_gA = (size_t)(m0 + cp_r) * 1024 + cp_half * 8;
    const size_t cp_gB = (size_t)(n0 + cp_r) * 1024 + cp_half * 8;

    const int a_row = warp_m + (lane & 15);
    const int a_csel = (lane >> 4) << 3;
    const int b_row = warp_n + ((lane >> 4) << 3) + (lane & 7);
    const int b_csel = ((lane >> 3) & 1) << 3;

#pragma unroll
    for (int mb = 0; mb < 2; mb++)
#pragma unroll
        for (int nb = 0; nb < 8; nb++)
#pragma unroll
            for (int q = 0; q < 4; q++) acc[mb][nb][q] = 0.0f;

    auto issue = [&](int kc) {
        uint32_t st = sbase + (kc % 3) * GSTAGE;
        size_t kofs = (size_t)kc * 16;
        cp_async16(st + 0 * GBUF + cp_soff, Ah + cp_gA + kofs);
        cp_async16(st + 1 * GBUF + cp_soff, Al + cp_gA + kofs);
        cp_async16(st + 2 * GBUF + cp_soff, Bh + cp_gB + kofs);
        cp_async16(st + 3 * GBUF + cp_soff, Bl + cp_gB + kofs);
        CP_COMMIT();
    };

    issue(0);
    issue(1);
    for (int kc = 0; kc < 64; kc++) {
        if (kc < 63) { CP_WAIT(1); } else { CP_WAIT(0); }
        __syncthreads();                 // all warps past chunk kc-1
        if (kc + 2 < 64) issue(kc + 2);  // targets buffer (kc-1)%3, now free

        const uint32_t st = sbase + (kc % 3) * GSTAGE;
        uint32_t afh[2][4], afl[2][4];
#pragma unroll
        for (int mb = 0; mb < 2; mb++) {
            uint32_t off = (uint32_t)(((a_row + mb * 16) * GSTR + a_csel) * 2);
            ldsm_x4(afh[mb], st + 0 * GBUF + off);
            ldsm_x4(afl[mb], st + 1 * GBUF + off);
        }
#pragma unroll
        for (int nb2 = 0; nb2 < 4; nb2++) {
            uint32_t off = (uint32_t)(((b_row + nb2 * 16) * GSTR + b_csel) * 2);
            uint32_t th[4], tl[4];
            ldsm_x4(th, st + 2 * GBUF + off);
            ldsm_x4(tl, st + 3 * GBUF + off);
            uint32_t bh0[2] = {th[0], th[1]}, bh1[2] = {th[2], th[3]};
            uint32_t bl0[2] = {tl[0], tl[1]}, bl1[2] = {tl[2], tl[3]};
#pragma unroll
            for (int mb = 0; mb < 2; mb++) {
                mma_bf16(acc[mb][nb2 * 2],     afh[mb], bh0);
                mma_bf16(acc[mb][nb2 * 2 + 1], afh[mb], bh1);
                mma_bf16(acc[mb][nb2 * 2],     afh[mb], bl0);
                mma_bf16(acc[mb][nb2 * 2 + 1], afh[mb], bl1);
                mma_bf16(acc[mb][nb2 * 2],     afl[mb], bh0);
                mma_bf16(acc[mb][nb2 * 2 + 1], afl[mb], bh1);
            }
        }
    }
}

// projection GEMM: out_mode 1 -> bf16 hi/lo split [B,H,T,D]; 0 -> fp32 [M,N]
__global__ void __launch_bounds__(256, 2) gemm_cp_kernel(
    const unsigned short* __restrict__ Ah, const unsigned short* __restrict__ Al,
    const unsigned short* __restrict__ Bh, const unsigned short* __restrict__ Bl,
    const float* __restrict__ bias, float scale, int out_mode,
    float* __restrict__ Cf, unsigned short* __restrict__ Ch,
    unsigned short* __restrict__ Cl)
{
    extern __shared__ char smem[];
    const int tid = threadIdx.x, wid = tid >> 5, lane = tid & 31;
    const int m0 = blockIdx.x * 128, n0 = blockIdx.y * 128;

    float acc[2][8][4];
    gemm_body(Ah, Al, Bh, Bl, smem, m0, n0, acc);

    const int warp_m = (wid & 3) * 32;
    const int warp_n = (wid >> 2) * 64;
    const int g = lane >> 2, tg = lane & 3;
#pragma unroll
    for (int mb = 0; mb < 2; mb++) {
#pragma unroll
        for (int nb = 0; nb < 8; nb++) {
            int n = n0 + warp_n + nb * 8 + tg * 2;
            float b0 = bias[n], b1 = bias[n + 1];
#pragma unroll
            for (int half = 0; half < 2; half++) {
                int m = m0 + warp_m + mb * 16 + g + half * 8;
                float vx = (acc[mb][nb][half * 2 + 0] + b0) * scale;
                float vy = (acc[mb][nb][half * 2 + 1] + b1) * scale;
                if (out_mode == 1) {
                    int bb = m >> 10, t = m & 1023, hh = n >> 6, d = n & 63;
                    size_t off = (((size_t)(bb * NH + hh)) * TLEN + t) * HD + d;
                    float hx = bf16_round(vx), hy = bf16_round(vy);
                    *(uint32_t*)(Ch + off) = pack_bf16x2(hx, hy);
                    *(uint32_t*)(Cl + off) = pack_bf16x2(vx - hx, vy - hy);
                } else {
                    float2 v; v.x = vx; v.y = vy;
                    *(float2*)(Cf + (size_t)m * 1024 + n) = v;
                }
            }
        }
    }
}

// ---------------- tensor-core flash attention (64-row tiles, K/V dbl-buf) ---
// CTA: 128 threads (4 warps), forced 3 CTAs/SM. Grid (16,16,4).
#define FPAD 72
#define FBUF (64 * FPAD * 2)   // 9216 bytes

__global__ void __launch_bounds__(128, 3) flash_mma_kernel(
    const float* __restrict__ attn_bias)
{
    extern __shared__ char sm[];
    float* smask = (float*)(sm + 8 * FBUF);

    const int tid = threadIdx.x, wid = tid >> 5, lane = tid & 31;
    const int t0 = blockIdx.x * 64, h = blockIdx.y, b = blockIdx.z;
    const int bh = b * NH + h;
    const size_t base = (size_t)bh * TLEN * HD;
    const unsigned short *qh_g = g_qh + base, *ql_g = g_ql + base;
    const unsigned short *kh_g = g_kh + base, *kl_g = g_kl + base;
    const unsigned short *vh_g = g_vh + base, *vl_g = g_vl + base;
    const float* biasbase = attn_bias + (size_t)bh * TLEN * TLEN;

    const int warp_m = wid * 16;
    const int g = lane >> 2, tq = lane & 3;
    const uint32_t sb = smem_u32(sm);

    auto issue_kv = [&](int step) {
        uint32_t bufs = sb + ((step & 1) ? 4u : 0u) * FBUF;
        int s0 = step * 64;
#pragma unroll
        for (int rep = 0; rep < 4; rep++) {
            int i = rep * 128 + tid;
            int r = i >> 3, c8 = (i & 7) << 3;
            uint32_t so = (uint32_t)(r * (FPAD * 2) + c8 * 2);
            size_t go = (size_t)(s0 + r) * HD + c8;
            cp_async16(bufs + 0 * FBUF + so, kh_g + go);
            cp_async16(bufs + 1 * FBUF + so, kl_g + go);
            cp_async16(bufs + 2 * FBUF + so, vh_g + go);
            cp_async16(bufs + 3 * FBUF + so, vl_g + go);
        }
        CP_COMMIT();
    };

    issue_kv(0);

    // Q staged through bufs 4,5 (consumed into fragments before stage 1 lands)
    unsigned short* sQh = (unsigned short*)(sm + 4 * FBUF);
    unsigned short* sQl = (unsigned short*)(sm + 5 * FBUF);
    for (int i = tid; i < 1024; i += 128) {
        int r = i >> 4, c4 = (i & 15) << 2;
        size_t go = (size_t)(t0 + r) * HD + c4;
        *(uint2*)&sQh[r * FPAD + c4] = *(const uint2*)(qh_g + go);
        *(uint2*)&sQl[r * FPAD + c4] = *(const uint2*)(ql_g + go);
    }
    __syncthreads();

    const int a_row = warp_m + (lane & 15);
    const int a_csel = (lane >> 4) << 3;
    uint32_t qh[4][4], ql[4][4];
#pragma unroll
    for (int kk = 0; kk < 4; kk++) {
        uint32_t off = (uint32_t)((a_row * FPAD + kk * 16 + a_csel) * 2);
        ldsm_x4(qh[kk], sb + 4 * FBUF + off);
        ldsm_x4(ql[kk], sb + 5 * FBUF + off);
    }
    __syncthreads();

    issue_kv(1);

    float accO[8][4];
#pragma unroll
    for (int nb = 0; nb < 8; nb++)
#pragma unroll
        for (int q = 0; q < 4; q++) accO[nb][q] = 0.0f;
    float mrow0 = -1e30f, mrow1 = -1e30f, lrow0 = 0.0f, lrow1 = 0.0f;

    const int b_rowbase = ((lane >> 4) << 3) + (lane & 7);
    const int b_csel = ((lane >> 3) & 1) << 3;
    const int v_key = (((lane >> 3) & 1) << 3) + (lane & 7);
    const int v_dof = (lane >> 4) << 3;

    for (int it = 0; it < 16; it++) {
        const int s0 = it * 64;
        if (it < 15) { CP_WAIT(1); } else { CP_WAIT(0); }
        if (tid < 64) smask[tid] = g_maskval[b * TLEN + s0 + tid];
        __syncthreads();

        const uint32_t bufs = sb + ((it & 1) ? 4u : 0u) * FBUF;
        const uint32_t kh_b = bufs, kl_b = bufs + FBUF;
        const uint32_t vh_b = bufs + 2 * FBUF, vl_b = bufs + 3 * FBUF;

        // ---- S = Qh*Kh + Qh*Kl + Ql*Kh ----
        float accS[8][4];
#pragma unroll
        for (int nb = 0; nb < 8; nb++)
#pragma unroll
            for (int q = 0; q < 4; q++) accS[nb][q] = 0.0f;

#pragma unroll
        for (int kk = 0; kk < 4; kk++) {
#pragma unroll
            for (int nb2 = 0; nb2 < 4; nb2++) {
                uint32_t off = (uint32_t)(((b_rowbase + nb2 * 16) * FPAD + kk * 16 + b_csel) * 2);
                uint32_t th[4], tl[4];
                ldsm_x4(th, kh_b + off);
                ldsm_x4(tl, kl_b + off);
                uint32_t bh0[2] = {th[0], th[1]}, bh1[2] = {th[2], th[3]};
                uint32_t bl0[2] = {tl[0], tl[1]}, bl1[2] = {tl[2], tl[3]};
                mma_bf16(accS[nb2 * 2],     qh[kk], bh0);
                mma_bf16(accS[nb2 * 2 + 1], qh[kk], bh1);
                mma_bf16(accS[nb2 * 2],     qh[kk], bl0);
                mma_bf16(accS[nb2 * 2 + 1], qh[kk], bl1);
                mma_bf16(accS[nb2 * 2],     ql[kk], bh0);
                mma_bf16(accS[nb2 * 2 + 1], ql[kk], bh1);
            }
        }

        // ---- add bias + mask ----
        const int row0 = t0 + warp_m + g;
        const int row1 = row0 + 8;
#pragma unroll
        for (int nb = 0; nb < 8; nb++) {
            int col = s0 + nb * 8 + tq * 2;
            float2 bv0 = *(const float2*)(biasbase + (size_t)row0 * TLEN + col);
            float2 bv1 = *(const float2*)(biasbase + (size_t)row1 * TLEN + col);
            float mk0 = smask[nb * 8 + tq * 2];
            float mk1 = smask[nb * 8 + tq * 2 + 1];
            accS[nb][0] += bv0.x + mk0;
            accS[nb][1] += bv0.y + mk1;
            accS[nb][2] += bv1.x + mk0;
            accS[nb][3] += bv1.y + mk1;
        }

        // ---- online softmax (quad reductions) ----
        float mx0 = mrow0, mx1 = mrow1;
#pragma unroll
        for (int nb = 0; nb < 8; nb++) {
            mx0 = fmaxf(mx0, fmaxf(accS[nb][0], accS[nb][1]));
            mx1 = fmaxf(mx1, fmaxf(accS[nb][2], accS[nb][3]));
        }
        mx0 = fmaxf(mx0, __shfl_xor_sync(0xFFFFFFFF, mx0, 1));
        mx0 = fmaxf(mx0, __shfl_xor_sync(0xFFFFFFFF, mx0, 2));
        mx1 = fmaxf(mx1, __shfl_xor_sync(0xFFFFFFFF, mx1, 1));
        mx1 = fmaxf(mx1, __shfl_xor_sync(0xFFFFFFFF, mx1, 2));
        float al0 = __expf(mrow0 - mx0), al1 = __expf(mrow1 - mx1);
        mrow0 = mx0; mrow1 = mx1;

        float sum0 = 0.0f, sum1 = 0.0f;
#pragma unroll
        for (int nb = 0; nb < 8; nb++) {
            accS[nb][0] = __expf(accS[nb][0] - mx0);
            accS[nb][1] = __expf(accS[nb][1] - mx0);
            accS[nb][2] = __expf(accS[nb][2] - mx1);
            accS[nb][3] = __expf(accS[nb][3] - mx1);
            sum0 += accS[nb][0] + accS[nb][1];
            sum1 += accS[nb][2] + accS[nb][3];
        }
        sum0 += __shfl_xor_sync(0xFFFFFFFF, sum0, 1);
        sum0 += __shfl_xor_sync(0xFFFFFFFF, sum0, 2);
        sum1 += __shfl_xor_sync(0xFFFFFFFF, sum1, 1);
        sum1 += __shfl_xor_sync(0xFFFFFFFF, sum1, 2);
        lrow0 = lrow0 * al0 + sum0;
        lrow1 = lrow1 * al1 + sum1;

#pragma unroll
        for (int nb = 0; nb < 8; nb++) {
            accO[nb][0] *= al0; accO[nb][1] *= al0;
            accO[nb][2] *= al1; accO[nb][3] *= al1;
        }

        // ---- PV: O += Ph*Vh + Ph*Vl + Pl*Vh ----
#pragma unroll
        for (int ks = 0; ks < 4; ks++) {
            float p00 = accS[2 * ks][0],     p01 = accS[2 * ks][1];
            float p02 = accS[2 * ks][2],     p03 = accS[2 * ks][3];
            float p10 = accS[2 * ks + 1][0], p11 = accS[2 * ks + 1][1];
            float p12 = accS[2 * ks + 1][2], p13 = accS[2 * ks + 1][3];
            float h00 = bf16_round(p00), h01 = bf16_round(p01);
            float h02 = bf16_round(p02), h03 = bf16_round(p03);
            float h10 = bf16_round(p10), h11 = bf16_round(p11);
            float h12 = bf16_round(p12), h13 = bf16_round(p13);
            uint32_t ph[4], pl[4];
            ph[0] = pack_bf16x2(h00, h01);
            ph[1] = pack_bf16x2(h02, h03);
            ph[2] = pack_bf16x2(h10, h11);
            ph[3] = pack_bf16x2(h12, h13);
            pl[0] = pack_bf16x2(p00 - h00, p01 - h01);
            pl[1] = pack_bf16x2(p02 - h02, p03 - h03);
            pl[2] = pack_bf16x2(p10 - h10, p11 - h11);
            pl[3] = pack_bf16x2(p12 - h12, p13 - h13);

#pragma unroll
            for (int db2 = 0; db2 < 4; db2++) {
                uint32_t addr = (uint32_t)(((ks * 16 + v_key) * FPAD
                                            + db2 * 16 + v_dof) * 2);
                uint32_t tvh[4], tvl[4];
                ldsm_x4_t(tvh, vh_b + addr);
                ldsm_x4_t(tvl, vl_b + addr);
                uint32_t bh0[2] = {tvh[0], tvh[1]}, bh1[2] = {tvh[2], tvh[3]};
                uint32_t bl0[2] = {tvl[0], tvl[1]}, bl1[2] = {tvl[2], tvl[3]};
                mma_bf16(accO[db2 * 2],     ph, bh0);
                mma_bf16(accO[db2 * 2 + 1], ph, bh1);
                mma_bf16(accO[db2 * 2],     ph, bl0);
                mma_bf16(accO[db2 * 2 + 1], ph, bl1);
                mma_bf16(accO[db2 * 2],     pl, bh0);
                mma_bf16(accO[db2 * 2 + 1], pl, bh1);
            }
        }

        __syncthreads();
        if (it + 2 < 16) issue_kv(it + 2);
    }

    // ---- epilogue: O /= l, write pre-split ctx [B,T,E] ----
    float li0 = 1.0f / lrow0, li1 = 1.0f / lrow1;
    const int row0 = t0 + warp_m + g;
    const int row1 = row0 + 8;
#pragma unroll
    for (int nb = 0; nb < 8; nb++) {
        int d = h * HD + nb * 8 + tq * 2;
        float o0x = accO[nb][0] * li0, o0y = accO[nb][1] * li0;
        float o1x = accO[nb][2] * li1, o1y = accO[nb][3] * li1;
        size_t off0 = ((size_t)(b * TLEN + row0)) * EE + d;
        size_t off1 = ((size_t)(b * TLEN + row1)) * EE + d;
        float h0x = bf16_round(o0x), h0y = bf16_round(o0y);
        float h1x = bf16_round(o1x), h1y = bf16_round(o1y);
        *(uint32_t*)(g_cx_h + off0) = pack_bf16x2(h0x, h0y);
        *(uint32_t*)(g_cx_l + off0) = pack_bf16x2(o0x - h0x, o0y - h0y);
        *(uint32_t*)(g_cx_h + off1) = pack_bf16x2(h1x, h1y);
        *(uint32_t*)(g_cx_l + off1) = pack_bf16x2(o1x - h1x, o1y - h1y);
    }
}

// ---------------- launch ----------------------------------------------------
extern "C" void kernel_launch(void* const* d_in, const int* in_sizes, int n_in,
                              void* d_out, int out_size) {
    const float* query     = (const float*)d_in[0];
    const float* key       = (const float*)d_in[1];
    const float* value     = (const float*)d_in[2];
    const void*  mask      = d_in[3];
    const float* attn_bias = (const float*)d_in[4];
    const float* wq = (const float*)d_in[5];
    const float* bq = (const float*)d_in[6];
    const float* wk = (const float*)d_in[7];
    const float* bk = (const float*)d_in[8];
    const float* wv = (const float*)d_in[9];
    const float* bv = (const float*)d_in[10];
    const float* wo = (const float*)d_in[11];
    const float* bo = (const float*)d_in[12];
    float* out = (float*)d_out;

    unsigned short *xqh, *xql, *xkh, *xkl, *xvh, *xvl, *cxh, *cxl;
    unsigned short *wqh, *wql, *wkh, *wkl, *wvh, *wvl, *woh, *wol;
    unsigned short *qh, *ql, *kh, *kl, *vh, *vl;
    cudaGetSymbolAddress((void**)&xqh, g_xq_h); cudaGetSymbolAddress((void**)&xql, g_xq_l);
    cudaGetSymbolAddress((void**)&xkh, g_xk_h); cudaGetSymbolAddress((void**)&xkl, g_xk_l);
    cudaGetSymbolAddress((void**)&xvh, g_xv_h); cudaGetSymbolAddress((void**)&xvl, g_xv_l);
    cudaGetSymbolAddress((void**)&cxh, g_cx_h); cudaGetSymbolAddress((void**)&cxl, g_cx_l);
    cudaGetSymbolAddress((void**)&wqh, g_wq_h); cudaGetSymbolAddress((void**)&wql, g_wq_l);
    cudaGetSymbolAddress((void**)&wkh, g_wk_h); cudaGetSymbolAddress((void**)&wkl, g_wk_l);
    cudaGetSymbolAddress((void**)&wvh, g_wv_h); cudaGetSymbolAddress((void**)&wvl, g_wv_l);
    cudaGetSymbolAddress((void**)&woh, g_wo_h); cudaGetSymbolAddress((void**)&wol, g_wo_l);
    cudaGetSymbolAddress((void**)&qh, g_qh); cudaGetSymbolAddress((void**)&ql, g_ql);
    cudaGetSymbolAddress((void**)&kh, g_kh); cudaGetSymbolAddress((void**)&kl, g_kl);
    cudaGetSymbolAddress((void**)&vh, g_vh); cudaGetSymbolAddress((void**)&vl, g_vl);

    detect_mask_kernel<<<1, 256>>>((const unsigned char*)mask);
    expand_mask_kernel<<<(BB * TLEN + 255) / 256, 256>>>(mask);

    int act4 = ACT_ELEMS / 4, w4 = W_ELEMS / 4;

    SplitArgs sa;
    sa.src[0] = query; sa.hi[0] = xqh; sa.lo[0] = xql;
    sa.src[1] = key;   sa.hi[1] = xkh; sa.lo[1] = xkl;
    sa.src[2] = value; sa.hi[2] = xvh; sa.lo[2] = xvl;
    sa.src[3] = query; sa.hi[3] = xqh; sa.lo[3] = xql;
    sa.n4 = act4;
    split_multi_kernel<<<dim3((act4 + 255) / 256, 1, 3), 256>>>(sa);

    SplitArgs sw;
    sw.src[0] = wq; sw.hi[0] = wqh; sw.lo[0] = wql;
    sw.src[1] = wk; sw.hi[1] = wkh; sw.lo[1] = wkl;
    sw.src[2] = wv; sw.hi[2] = wvh; sw.lo[2] = wvl;
    sw.src[3] = wo; sw.hi[3] = woh; sw.lo[3] = wol;
    sw.n4 = w4;
    split_multi_kernel<<<dim3((w4 + 255) / 256, 1, 4), 256>>>(sw);

    cudaFuncSetAttribute(gemm_cp_kernel, cudaFuncAttributeMaxDynamicSharedMemorySize,
                         GSMEM);
    dim3 gg(32, 8);
    gemm_cp_kernel<<<gg, 256, GSMEM>>>(xqh, xql, wqh, wql, bq, SCALING, 1,
                                       nullptr, qh, ql);
    gemm_cp_kernel<<<gg, 256, GSMEM>>>(xkh, xkl, wkh, wkl, bk, 1.0f, 1,
                                       nullptr, kh, kl);
    gemm_cp_kernel<<<gg, 256, GSMEM>>>(xvh, xvl, wvh, wvl, bv, 1.0f, 1,
                                       nullptr, vh, vl);

    const int flash_smem = 8 * FBUF + 64 * (int)sizeof(float);
    cudaFuncSetAttribute(flash_mma_kernel,
                         cudaFuncAttributeMaxDynamicSharedMemorySize, flash_smem);
    flash_mma_kernel<<<dim3(16, 16, 4), 128, flash_smem>>>(attn_bias);

    gemm_cp_kernel<<<gg, 256, GSMEM>>>(cxh, cxl, woh, wol, bo, 1.0f, 0,
                                       out, nullptr, nullptr);
}